// round 6
// baseline (speedup 1.0000x reference)
#include <cuda_runtime.h>
#include <cuda_bf16.h>

// Problem constants (fixed by the reference)
#define BMAX 524288
constexpr int   C_CLS = 330;
constexpr int   NF2   = C_CLS / 2;               // 165 float2 per row
constexpr float TAU   = 5.799092654460526f;      // ln(330)
constexpr float LAM   = 0.25f;
constexpr float EPSV  = 0.1f;
constexpr float E_F   = 2.718281828459045f;
constexpr float NEG2E = -0.7357588823428847f;    // -2/e

// Scratch (allocation-free rule: __device__ globals)
__device__ float  g_l[BMAX];      // per-row NLL l_i
__device__ float  g_sm[BMAX];     // per-row -sum_c log p
__device__ double g_acc[2];       // [0]=smooth sum, [1]=super sum

// ---------------------------------------------------------------------------
// Kernel 1: one warp per row. Single HBM pass: registers hold the whole row.
// ---------------------------------------------------------------------------
__global__ __launch_bounds__(256) void row_kernel(
    const float* __restrict__ x, const int* __restrict__ tgt, int B)
{
    int row  = blockIdx.x * 8 + (threadIdx.x >> 5);
    if (row >= B) return;
    int lane = threadIdx.x & 31;

    const float2* p = reinterpret_cast<const float2*>(x + (size_t)row * C_CLS);

    float2 v[6];
    float mx = -1e30f, sx = 0.f;
#pragma unroll
    for (int k = 0; k < 6; k++) {
        int idx = k * 32 + lane;
        float2 t;
        if (idx < NF2) t = __ldg(p + idx);
        else           t = make_float2(-1e30f, -1e30f);   // exp underflows to 0
        v[k] = t;
        mx = fmaxf(mx, fmaxf(t.x, t.y));
        sx += (idx < NF2) ? (t.x + t.y) : 0.f;
    }
#pragma unroll
    for (int o = 16; o > 0; o >>= 1) {
        mx  = fmaxf(mx, __shfl_xor_sync(0xffffffffu, mx, o));
        sx += __shfl_xor_sync(0xffffffffu, sx, o);
    }

    float se = 0.f;
#pragma unroll
    for (int k = 0; k < 6; k++)
        se += __expf(v[k].x - mx) + __expf(v[k].y - mx);   // MUFU EX2 path
#pragma unroll
    for (int o = 16; o > 0; o >>= 1)
        se += __shfl_xor_sync(0xffffffffu, se, o);

    if (lane == 0) {
        float logZ = mx + __logf(se);
        int   t    = tgt[row];
        float xt   = __ldg(x + (size_t)row * C_CLS + t);   // L1 hit (just loaded)
        g_l[row]   = logZ - xt;                            // l_i
        g_sm[row]  = (float)C_CLS * logZ - sx;             // -sum_c log p
    }
}

// ---------------------------------------------------------------------------
// Kernel 2: lane-parallel SuperLoss (one row per thread) + reduction.
// LambertW via the reference's exact recipe: branch-point series / log1p
// initial guess, 12 Halley iterations with identical safe-clamps.
// ---------------------------------------------------------------------------
__global__ __launch_bounds__(256) void super_kernel(int B)
{
    float ssm = 0.f, ssp = 0.f;
    int stride = gridDim.x * blockDim.x;
    for (int i = blockIdx.x * blockDim.x + threadIdx.x; i < B; i += stride) {
        ssm += g_sm[i];
        float l = g_l[i];

        float y  = 0.5f * fmaxf(NEG2E, (l - TAU) * 4.0f);  // /LAM, LAM=0.25
        float pb = sqrtf(fmaxf(2.f * (E_F * y + 1.f), 0.f));
        float wbp = -1.f + pb - pb * pb * (1.f / 3.f)
                    + (11.f / 72.f) * pb * pb * pb;
        float w = (y < 0.3f) ? wbp : log1pf(y);
#pragma unroll 1
        for (int it = 0; it < 12; it++) {
            float ew   = expf(w);
            float f    = w * ew - y;
            float wp1  = w + 1.f;
            float swp1 = (fabsf(wp1) < 1e-12f) ? 1e-12f : wp1;
            float den  = ew * wp1 - (w + 2.f) * f / (2.f * swp1);
            float sden = (fabsf(den) < 1e-30f) ? 1e-30f : den;
            float step = (fabsf(f) < 1e-30f) ? 0.f : f / sden;
            w -= step;
        }
        float sigma = expf(-w);
        ssp += (l - TAU) * sigma + LAM * w * w;
    }

    // warp + block reduce, one double atomic per block per accumulator
    __shared__ float s1[32], s2[32];
    int lane = threadIdx.x & 31, wid = threadIdx.x >> 5;
#pragma unroll
    for (int o = 16; o > 0; o >>= 1) {
        ssm += __shfl_xor_sync(0xffffffffu, ssm, o);
        ssp += __shfl_xor_sync(0xffffffffu, ssp, o);
    }
    if (lane == 0) { s1[wid] = ssm; s2[wid] = ssp; }
    __syncthreads();
    if (wid == 0) {
        int nw = blockDim.x >> 5;
        float a = (lane < nw) ? s1[lane] : 0.f;
        float b = (lane < nw) ? s2[lane] : 0.f;
#pragma unroll
        for (int o = 16; o > 0; o >>= 1) {
            a += __shfl_xor_sync(0xffffffffu, a, o);
            b += __shfl_xor_sync(0xffffffffu, b, o);
        }
        if (lane == 0) {
            atomicAdd(&g_acc[0], (double)a);
            atomicAdd(&g_acc[1], (double)b);
        }
    }
}

// ---------------------------------------------------------------------------
__global__ void zero_kernel() { g_acc[0] = 0.0; g_acc[1] = 0.0; }

__global__ void fin_kernel(float* __restrict__ out, int B)
{
    double sm = g_acc[0] / (double)B;   // loss_smooth
    double sp = g_acc[1] / (double)B;   // super_loss
    out[0] = (float)(sm * ((double)EPSV / (double)C_CLS)
                     + (1.0 - (double)EPSV) * sp);
}

// ---------------------------------------------------------------------------
extern "C" void kernel_launch(void* const* d_in, const int* in_sizes, int n_in,
                              void* d_out, int out_size)
{
    const float* x   = (const float*)d_in[0];   // output [B, 330] f32
    const int*   tgt = (const int*)d_in[1];     // target [B] i32
    int B = in_sizes[1];
    if (B > BMAX) B = BMAX;

    zero_kernel<<<1, 1>>>();
    int nblk = (B + 7) / 8;                     // 8 warps (rows) per block
    row_kernel<<<nblk, 256>>>(x, tgt, B);
    super_kernel<<<1024, 256>>>(B);
    fin_kernel<<<1, 1>>>((float*)d_out, B);
}